// round 1
// baseline (speedup 1.0000x reference)
#include <cuda_runtime.h>
#include <math.h>

#define BB 8
#define NN 2048
#define EE 64
#define DD 256
#define ROWS (BB*NN)   // 16384

// ---------------- scratch (static device globals; no allocs) ----------------
__device__ float g_xn[ROWS*EE];
__device__ float g_q [ROWS*DD];
__device__ float g_k [ROWS*DD];
__device__ float g_v [ROWS*DD];
__device__ float g_av[ROWS*DD];
__device__ float g_o1[ROWS*EE];
__device__ float g_Wp[768*64];
__device__ float g_bp[768];

// ---------------- helpers ----------------
__device__ __forceinline__ float wsum(float v){
    v += __shfl_xor_sync(0xffffffffu, v, 16);
    v += __shfl_xor_sync(0xffffffffu, v, 8);
    v += __shfl_xor_sync(0xffffffffu, v, 4);
    v += __shfl_xor_sync(0xffffffffu, v, 2);
    v += __shfl_xor_sync(0xffffffffu, v, 1);
    return v;
}
__device__ __forceinline__ float wmaxr(float v){
    v = fmaxf(v, __shfl_xor_sync(0xffffffffu, v, 16));
    v = fmaxf(v, __shfl_xor_sync(0xffffffffu, v, 8));
    v = fmaxf(v, __shfl_xor_sync(0xffffffffu, v, 4));
    v = fmaxf(v, __shfl_xor_sync(0xffffffffu, v, 2));
    v = fmaxf(v, __shfl_xor_sync(0xffffffffu, v, 1));
    return v;
}
__device__ __forceinline__ float softplusf(float x){
    if (x > 20.f) return x;
    return log1pf(expf(x));
}

// ---------------- fold: W_eff = m_w @ w_w, b_eff = m_w @ w_b + m_b ----------
// packed rows: [0,256)=q  [256,512)=k  [512,768)=v(copy)
__global__ void k_fold(const float* __restrict__ wq_w, const float* __restrict__ wq_b,
                       const float* __restrict__ wk_w, const float* __restrict__ wk_b,
                       const float* __restrict__ wv_w, const float* __restrict__ wv_b,
                       const float* __restrict__ mq_w, const float* __restrict__ mq_b,
                       const float* __restrict__ mk_w, const float* __restrict__ mk_b){
    int r = blockIdx.x, e = threadIdx.x;
    if (r < 256){
        float acc = 0.f;
        for (int c = 0; c < 256; c++) acc += mq_w[r*256+c]*wq_w[c*64+e];
        g_Wp[r*64+e] = acc;
        if (e == 0){
            float bb = mq_b[r];
            for (int c = 0; c < 256; c++) bb += mq_w[r*256+c]*wq_b[c];
            g_bp[r] = bb;
        }
    } else if (r < 512){
        int rr = r - 256;
        float acc = 0.f;
        for (int c = 0; c < 256; c++) acc += mk_w[rr*256+c]*wk_w[c*64+e];
        g_Wp[r*64+e] = acc;
        if (e == 0){
            float bb = mk_b[rr];
            for (int c = 0; c < 256; c++) bb += mk_w[rr*256+c]*wk_b[c];
            g_bp[r] = bb;
        }
    } else {
        int rr = r - 512;
        g_Wp[r*64+e] = wv_w[rr*64+e];
        if (e == 0) g_bp[r] = wv_b[rr];
    }
}

// ---------------- LayerNorm over E=64: one warp per row ----------------
__global__ __launch_bounds__(256) void k_ln(const float* __restrict__ x,
                                            const float* __restrict__ g,
                                            const float* __restrict__ be){
    int t = threadIdx.x, lane = t & 31, w = t >> 5;
    size_t row = (size_t)blockIdx.x*8 + w;
    const float* xr = x + row*64;
    float x0 = xr[lane], x1 = xr[lane+32];
    float mean = wsum(x0+x1)*(1.f/64.f);
    float msq  = wsum(x0*x0+x1*x1)*(1.f/64.f);
    float rs = rsqrtf(msq - mean*mean + 1e-5f);
    float* o = g_xn + row*64;
    o[lane]    = (x0-mean)*rs*g[lane]    + be[lane];
    o[lane+32] = (x1-mean)*rs*g[lane+32] + be[lane+32];
}

// ---------------- QKV GEMM: [16384,64] @ [768,64]^T (K=64, single step) -----
__global__ __launch_bounds__(256) void k_qkv(){
    __shared__ float sA[64*68];
    __shared__ float sB[64*68];
    int m0 = blockIdx.x*64, n0 = blockIdx.y*64;
    int t = threadIdx.x;
    for (int i = t; i < 1024; i += 256){
        int r = i >> 4, c = i & 15;
        *(float4*)&sA[r*68 + c*4] = *(const float4*)&g_xn[((size_t)(m0+r))*64 + c*4];
        *(float4*)&sB[r*68 + c*4] = *(const float4*)&g_Wp[(n0+r)*64 + c*4];
    }
    __syncthreads();
    int cg = t & 15, rg = t >> 4;
    float acc[4][4] = {};
    #pragma unroll 4
    for (int e4 = 0; e4 < 16; e4++){
        float4 av[4], bv[4];
        #pragma unroll
        for (int i = 0; i < 4; i++) av[i] = *(const float4*)&sA[(rg+16*i)*68 + e4*4];
        #pragma unroll
        for (int j = 0; j < 4; j++) bv[j] = *(const float4*)&sB[(cg+16*j)*68 + e4*4];
        #pragma unroll
        for (int i = 0; i < 4; i++)
            #pragma unroll
            for (int j = 0; j < 4; j++)
                acc[i][j] += av[i].x*bv[j].x + av[i].y*bv[j].y + av[i].z*bv[j].z + av[i].w*bv[j].w;
    }
    #pragma unroll
    for (int i = 0; i < 4; i++){
        size_t m = m0 + rg + 16*i;
        #pragma unroll
        for (int j = 0; j < 4; j++){
            int n = n0 + cg + 16*j;
            float val = acc[i][j] + g_bp[n];
            if (n < 256)       g_q[m*256 + n]       = val;
            else if (n < 512)  g_k[m*256 + (n-256)] = val;
            else               g_v[m*256 + (n-512)] = val;
        }
    }
}

// ---------------- fused attention: two-pass, never materializes NxN ---------
// pass1: per (query,head) running max m_h and sumexp l_h over all keys
// pass2: c_ij = w_j * sum_h exp(s-m_h)/l_h ; att_out = (c @ v) / (c @ 1)
#define QS 260                      // smem row stride (words): %32==4 -> conflict-free f4
#define SQ_OFF 0                    // 32 x 260
#define SK_OFF (32*QS)              // 64 x 260 (pass2: rows 0..31 = K, 32..63 = V)
#define SC_OFF (SK_OFF + 64*QS)     // 32 x 33
#define SW_OFF (SC_OFF + 32*33)     // 64
#define ATTN_SMEM ((SW_OFF + 64)*4) // = 104320 bytes

__global__ void __launch_bounds__(256,2) k_attn(const float* __restrict__ gw){
    extern __shared__ float sm[];
    float* sQ = sm + SQ_OFF;
    float* sK = sm + SK_OFF;
    float* sC = sm + SC_OFF;
    float* sW = sm + SW_OFF;
    int t = threadIdx.x, lane = t & 31, wrp = t >> 5;
    int b  = blockIdx.x >> 6;        // 64 query-tiles of 32 per batch
    int qt = blockIdx.x & 63;
    const float* qbase = g_q + ((size_t)(b*2048 + qt*32))*256;
    const float* kbase = g_k + (size_t)b*2048*256;
    const float* vbase = g_v + (size_t)b*2048*256;
    const float* wbase = gw  + (size_t)b*2048;

    // load Q tile (32 x 256)
    for (int i = t; i < 2048; i += 256){
        int r = i >> 6, c = i & 63;
        *(float4*)&sQ[r*QS + c*4] = *(const float4*)&qbase[r*256 + c*4];
    }

    float rm[4][4], rl[4][4];
    #pragma unroll
    for (int ii = 0; ii < 4; ii++)
        #pragma unroll
        for (int h = 0; h < 4; h++){ rm[ii][h] = -INFINITY; rl[ii][h] = 0.f; }

    // ---- pass 1: key tiles of 64 ----
    for (int j0 = 0; j0 < 2048; j0 += 64){
        __syncthreads();
        for (int i = t; i < 4096; i += 256){
            int r = i >> 6, c = i & 63;
            *(float4*)&sK[r*QS + c*4] = *(const float4*)&kbase[(size_t)(j0+r)*256 + c*4];
        }
        if (t < 64) sW[t] = wbase[j0 + t];
        __syncthreads();
        float w0 = sW[lane], w1 = sW[lane+32];
        #pragma unroll
        for (int h = 0; h < 4; h++){
            float s0[4] = {0,0,0,0}, s1[4] = {0,0,0,0};
            const float* kr0 = &sK[lane*QS + h*64];
            const float* kr1 = &sK[(lane+32)*QS + h*64];
            #pragma unroll 4
            for (int e4 = 0; e4 < 16; e4++){
                float4 k0 = *(const float4*)&kr0[e4*4];
                float4 k1 = *(const float4*)&kr1[e4*4];
                #pragma unroll
                for (int ii = 0; ii < 4; ii++){
                    float4 qv = *(const float4*)&sQ[(wrp*4+ii)*QS + h*64 + e4*4];
                    s0[ii] += qv.x*k0.x + qv.y*k0.y + qv.z*k0.z + qv.w*k0.w;
                    s1[ii] += qv.x*k1.x + qv.y*k1.y + qv.z*k1.z + qv.w*k1.w;
                }
            }
            #pragma unroll
            for (int ii = 0; ii < 4; ii++){
                float a  = (w0 == 0.f) ? -1e9f : s0[ii]*0.125f;
                float bs = (w1 == 0.f) ? -1e9f : s1[ii]*0.125f;
                float mt = wmaxr(fmaxf(a, bs));
                float lt = wsum(__expf(a - mt) + __expf(bs - mt));
                float nm = fmaxf(rm[ii][h], mt);
                rl[ii][h] = rl[ii][h]*__expf(rm[ii][h]-nm) + lt*__expf(mt-nm);
                rm[ii][h] = nm;
            }
        }
    }
    #pragma unroll
    for (int ii = 0; ii < 4; ii++)
        #pragma unroll
        for (int h = 0; h < 4; h++) rl[ii][h] = 1.f / rl[ii][h];

    // ---- pass 2: key+value tiles of 32, fused AV ----
    float acc[4][8] = {};
    float z[4] = {0,0,0,0};
    for (int j0 = 0; j0 < 2048; j0 += 32){
        __syncthreads();
        for (int i = t; i < 2048; i += 256){
            int r = i >> 6, c = i & 63;
            *(float4*)&sK[r*QS + c*4]      = *(const float4*)&kbase[(size_t)(j0+r)*256 + c*4];
            *(float4*)&sK[(32+r)*QS + c*4] = *(const float4*)&vbase[(size_t)(j0+r)*256 + c*4];
        }
        if (t < 32) sW[t] = wbase[j0 + t];
        __syncthreads();
        float wj = sW[lane];
        float cv[4] = {0,0,0,0};
        #pragma unroll
        for (int h = 0; h < 4; h++){
            float s[4] = {0,0,0,0};
            const float* kr = &sK[lane*QS + h*64];
            #pragma unroll 4
            for (int e4 = 0; e4 < 16; e4++){
                float4 k0 = *(const float4*)&kr[e4*4];
                #pragma unroll
                for (int ii = 0; ii < 4; ii++){
                    float4 qv = *(const float4*)&sQ[(wrp*4+ii)*QS + h*64 + e4*4];
                    s[ii] += qv.x*k0.x + qv.y*k0.y + qv.z*k0.z + qv.w*k0.w;
                }
            }
            #pragma unroll
            for (int ii = 0; ii < 4; ii++){
                float a = (wj == 0.f) ? -1e9f : s[ii]*0.125f;
                cv[ii] += __expf(a - rm[ii][h]) * rl[ii][h];
            }
        }
        #pragma unroll
        for (int ii = 0; ii < 4; ii++) sC[(wrp*4+ii)*33 + lane] = cv[ii]*wj;
        __syncthreads();
        #pragma unroll 4
        for (int j = 0; j < 32; j++){
            float4 v0 = *(const float4*)&sK[(32+j)*QS + lane*8];
            float4 v1 = *(const float4*)&sK[(32+j)*QS + lane*8 + 4];
            #pragma unroll
            for (int ii = 0; ii < 4; ii++){
                float c = sC[(wrp*4+ii)*33 + j];
                z[ii] += c;
                acc[ii][0] += c*v0.x; acc[ii][1] += c*v0.y;
                acc[ii][2] += c*v0.z; acc[ii][3] += c*v0.w;
                acc[ii][4] += c*v1.x; acc[ii][5] += c*v1.y;
                acc[ii][6] += c*v1.z; acc[ii][7] += c*v1.w;
            }
        }
    }
    float* obase = g_av + ((size_t)(b*2048 + qt*32))*256;
    #pragma unroll
    for (int ii = 0; ii < 4; ii++){
        float inv = 1.f / z[ii];
        float4 o0 = make_float4(acc[ii][0]*inv, acc[ii][1]*inv, acc[ii][2]*inv, acc[ii][3]*inv);
        float4 o1 = make_float4(acc[ii][4]*inv, acc[ii][5]*inv, acc[ii][6]*inv, acc[ii][7]*inv);
        *(float4*)&obase[(wrp*4+ii)*256 + lane*8]     = o0;
        *(float4*)&obase[(wrp*4+ii)*256 + lane*8 + 4] = o1;
    }
}

// ---------------- out1 = x + att_out @ out_w^T + out_b ----------------------
__global__ __launch_bounds__(256) void k_out1(const float* __restrict__ ow,
                                              const float* __restrict__ ob,
                                              const float* __restrict__ x){
    __shared__ float sA[64*68];
    __shared__ float sB[64*68];
    int m0 = blockIdx.x*64;
    int t = threadIdx.x;
    int cg = t & 15, rg = t >> 4;
    float acc[4][4] = {};
    for (int kc = 0; kc < 256; kc += 64){
        __syncthreads();
        for (int i = t; i < 1024; i += 256){
            int r = i >> 4, c = i & 15;
            *(float4*)&sA[r*68 + c*4] = *(const float4*)&g_av[((size_t)(m0+r))*256 + kc + c*4];
            *(float4*)&sB[r*68 + c*4] = *(const float4*)&ow[r*256 + kc + c*4];
        }
        __syncthreads();
        #pragma unroll 4
        for (int e4 = 0; e4 < 16; e4++){
            float4 av[4], bv[4];
            #pragma unroll
            for (int i = 0; i < 4; i++) av[i] = *(const float4*)&sA[(rg+16*i)*68 + e4*4];
            #pragma unroll
            for (int j = 0; j < 4; j++) bv[j] = *(const float4*)&sB[(cg+16*j)*68 + e4*4];
            #pragma unroll
            for (int i = 0; i < 4; i++)
                #pragma unroll
                for (int j = 0; j < 4; j++)
                    acc[i][j] += av[i].x*bv[j].x + av[i].y*bv[j].y + av[i].z*bv[j].z + av[i].w*bv[j].w;
        }
    }
    #pragma unroll
    for (int i = 0; i < 4; i++){
        size_t m = m0 + rg + 16*i;
        #pragma unroll
        for (int j = 0; j < 4; j++){
            int n = cg + 16*j;
            g_o1[m*64 + n] = acc[i][j] + ob[n] + x[m*64 + n];
        }
    }
}

// ---------------- final: out = LN(out1 + softplus(LN(out1)@ffn^T + fb)) -----
__global__ __launch_bounds__(256) void k_final(const float* __restrict__ g,
                                               const float* __restrict__ be,
                                               const float* __restrict__ fw,
                                               const float* __restrict__ fb,
                                               float* __restrict__ out){
    __shared__ float sFW[64*65];
    __shared__ float sy[8][64];
    int t = threadIdx.x, lane = t & 31, w = t >> 5;
    for (int i = t; i < 4096; i += 256) sFW[(i>>6)*65 + (i&63)] = fw[i];
    __syncthreads();
    size_t row = (size_t)blockIdx.x*8 + w;
    const float* o = g_o1 + row*64;
    float o0 = o[lane], o1 = o[lane+32];
    float mean = wsum(o0+o1)*(1.f/64.f);
    float msq  = wsum(o0*o0+o1*o1)*(1.f/64.f);
    float rs = rsqrtf(msq - mean*mean + 1e-5f);
    sy[w][lane]    = (o0-mean)*rs*g[lane]    + be[lane];
    sy[w][lane+32] = (o1-mean)*rs*g[lane+32] + be[lane+32];
    __syncwarp();
    float a0 = fb[lane], a1 = fb[lane+32];
    #pragma unroll 8
    for (int c = 0; c < 64; c++){
        float yv = sy[w][c];
        a0 += yv * sFW[lane*65 + c];
        a1 += yv * sFW[(lane+32)*65 + c];
    }
    float s0 = o0 + softplusf(a0);
    float s1 = o1 + softplusf(a1);
    float m2 = wsum(s0+s1)*(1.f/64.f);
    float q2 = wsum(s0*s0+s1*s1)*(1.f/64.f);
    float r2 = rsqrtf(q2 - m2*m2 + 1e-5f);
    out[row*64 + lane]    = (s0-m2)*r2*g[lane]    + be[lane];
    out[row*64 + lane+32] = (s1-m2)*r2*g[lane+32] + be[lane+32];
}

// ---------------- launch ----------------
extern "C" void kernel_launch(void* const* d_in, const int* in_sizes, int n_in,
                              void* d_out, int out_size){
    (void)in_sizes; (void)n_in; (void)out_size;
    const float* x     = (const float*)d_in[0];
    const float* wts   = (const float*)d_in[1];
    const float* ln_g  = (const float*)d_in[2];
    const float* ln_b  = (const float*)d_in[3];
    const float* wq_w  = (const float*)d_in[4];
    const float* wq_b  = (const float*)d_in[5];
    const float* wk_w  = (const float*)d_in[6];
    const float* wk_b  = (const float*)d_in[7];
    const float* wv_w  = (const float*)d_in[8];
    const float* wv_b  = (const float*)d_in[9];
    const float* mq_w  = (const float*)d_in[10];
    const float* mq_b  = (const float*)d_in[11];
    const float* mk_w  = (const float*)d_in[12];
    const float* mk_b  = (const float*)d_in[13];
    const float* out_w = (const float*)d_in[14];
    const float* out_b = (const float*)d_in[15];
    const float* ffn_w = (const float*)d_in[16];
    const float* ffn_b = (const float*)d_in[17];
    float* out = (float*)d_out;

    cudaFuncSetAttribute(k_attn, cudaFuncAttributeMaxDynamicSharedMemorySize, ATTN_SMEM);

    k_fold<<<768, 64>>>(wq_w, wq_b, wk_w, wk_b, wv_w, wv_b, mq_w, mq_b, mk_w, mk_b);
    k_ln<<<ROWS/8, 256>>>(x, ln_g, ln_b);
    k_qkv<<<dim3(ROWS/64, 12), 256>>>();
    k_attn<<<BB*NN/32, 256, ATTN_SMEM>>>(wts);
    k_out1<<<ROWS/64, 256>>>(out_w, out_b, x);
    k_final<<<ROWS/8, 256>>>(ln_g, ln_b, ffn_w, ffn_b, out);
}

// round 3
// speedup vs baseline: 5.2646x; 5.2646x over previous
#include <cuda_runtime.h>
#include <cuda_fp16.h>
#include <math.h>
#include <stdint.h>

#define BB 8
#define NN 2048
#define EE 64
#define DD 256
#define ROWS (BB*NN)   // 16384

// ---------------- scratch (static device globals; no allocs) ----------------
__device__ float g_xn[ROWS*EE];
__device__ __align__(16) __half g_q[ROWS*DD];
__device__ __align__(16) __half g_k[ROWS*DD];
__device__ __align__(16) __half g_v[ROWS*DD];
__device__ float g_av[ROWS*DD];
__device__ float g_o1[ROWS*EE];
__device__ float g_Wp[768*64];
__device__ float g_bp[768];

// ---------------- generic helpers ----------------
__device__ __forceinline__ float wsum(float v){
    v += __shfl_xor_sync(0xffffffffu, v, 16);
    v += __shfl_xor_sync(0xffffffffu, v, 8);
    v += __shfl_xor_sync(0xffffffffu, v, 4);
    v += __shfl_xor_sync(0xffffffffu, v, 2);
    v += __shfl_xor_sync(0xffffffffu, v, 1);
    return v;
}
__device__ __forceinline__ float softplusf(float x){
    if (x > 20.f) return x;
    return log1pf(expf(x));
}
__device__ __forceinline__ uint32_t smem_u32(const void* p){
    uint32_t a;
    asm("{ .reg .u64 t; cvta.to.shared.u64 t, %1; cvt.u32.u64 %0, t; }" : "=r"(a) : "l"(p));
    return a;
}

// ---------------- mma.sync / ldmatrix helpers (baseline PTX, sm_80+) --------
__device__ __forceinline__ void ldm_x4(uint32_t a[4], uint32_t addr){
    asm volatile("ldmatrix.sync.aligned.m8n8.x4.shared.b16 {%0,%1,%2,%3}, [%4];"
        : "=r"(a[0]), "=r"(a[1]), "=r"(a[2]), "=r"(a[3]) : "r"(addr));
}
__device__ __forceinline__ void ldm_x2(uint32_t a[2], uint32_t addr){
    asm volatile("ldmatrix.sync.aligned.m8n8.x2.shared.b16 {%0,%1}, [%2];"
        : "=r"(a[0]), "=r"(a[1]) : "r"(addr));
}
__device__ __forceinline__ void ldm_x2t(uint32_t a[2], uint32_t addr){
    asm volatile("ldmatrix.sync.aligned.m8n8.x2.trans.shared.b16 {%0,%1}, [%2];"
        : "=r"(a[0]), "=r"(a[1]) : "r"(addr));
}
__device__ __forceinline__ void mma16816(float c[4], const uint32_t a[4], const uint32_t b[2]){
    asm volatile("mma.sync.aligned.m16n8k16.row.col.f32.f16.f16.f32 "
        "{%0,%1,%2,%3}, {%4,%5,%6,%7}, {%8,%9}, {%0,%1,%2,%3};"
        : "+f"(c[0]), "+f"(c[1]), "+f"(c[2]), "+f"(c[3])
        : "r"(a[0]), "r"(a[1]), "r"(a[2]), "r"(a[3]), "r"(b[0]), "r"(b[1]));
}

// ---------------- fold: W_eff = m_w @ w_w, b_eff = m_w @ w_b + m_b ----------
__global__ void k_fold(const float* __restrict__ wq_w, const float* __restrict__ wq_b,
                       const float* __restrict__ wk_w, const float* __restrict__ wk_b,
                       const float* __restrict__ wv_w, const float* __restrict__ wv_b,
                       const float* __restrict__ mq_w, const float* __restrict__ mq_b,
                       const float* __restrict__ mk_w, const float* __restrict__ mk_b){
    int r = blockIdx.x, e = threadIdx.x;
    if (r < 256){
        float acc = 0.f;
        for (int c = 0; c < 256; c++) acc += mq_w[r*256+c]*wq_w[c*64+e];
        g_Wp[r*64+e] = acc;
        if (e == 0){
            float bb = mq_b[r];
            for (int c = 0; c < 256; c++) bb += mq_w[r*256+c]*wq_b[c];
            g_bp[r] = bb;
        }
    } else if (r < 512){
        int rr = r - 256;
        float acc = 0.f;
        for (int c = 0; c < 256; c++) acc += mk_w[rr*256+c]*wk_w[c*64+e];
        g_Wp[r*64+e] = acc;
        if (e == 0){
            float bb = mk_b[rr];
            for (int c = 0; c < 256; c++) bb += mk_w[rr*256+c]*wk_b[c];
            g_bp[r] = bb;
        }
    } else {
        int rr = r - 512;
        g_Wp[r*64+e] = wv_w[rr*64+e];
        if (e == 0) g_bp[r] = wv_b[rr];
    }
}

// ---------------- LayerNorm over E=64: one warp per row ----------------
__global__ __launch_bounds__(256) void k_ln(const float* __restrict__ x,
                                            const float* __restrict__ g,
                                            const float* __restrict__ be){
    int t = threadIdx.x, lane = t & 31, w = t >> 5;
    size_t row = (size_t)blockIdx.x*8 + w;
    const float* xr = x + row*64;
    float x0 = xr[lane], x1 = xr[lane+32];
    float mean = wsum(x0+x1)*(1.f/64.f);
    float msq  = wsum(x0*x0+x1*x1)*(1.f/64.f);
    float rs = rsqrtf(msq - mean*mean + 1e-5f);
    float* o = g_xn + row*64;
    o[lane]    = (x0-mean)*rs*g[lane]    + be[lane];
    o[lane+32] = (x1-mean)*rs*g[lane+32] + be[lane+32];
}

// ---------------- QKV GEMM -> fp16 Q/K/V [row][256] --------------------------
__global__ __launch_bounds__(256) void k_qkv(){
    __shared__ float sA[64*68];
    __shared__ float sB[64*68];
    int m0 = blockIdx.x*64, n0 = blockIdx.y*64;
    int t = threadIdx.x;
    for (int i = t; i < 1024; i += 256){
        int r = i >> 4, c = i & 15;
        *(float4*)&sA[r*68 + c*4] = *(const float4*)&g_xn[((size_t)(m0+r))*64 + c*4];
        *(float4*)&sB[r*68 + c*4] = *(const float4*)&g_Wp[(n0+r)*64 + c*4];
    }
    __syncthreads();
    int cg = t & 15, rg = t >> 4;
    float acc[4][4] = {};
    #pragma unroll 4
    for (int e4 = 0; e4 < 16; e4++){
        float4 av[4], bv[4];
        #pragma unroll
        for (int i = 0; i < 4; i++) av[i] = *(const float4*)&sA[(rg+16*i)*68 + e4*4];
        #pragma unroll
        for (int j = 0; j < 4; j++) bv[j] = *(const float4*)&sB[(cg+16*j)*68 + e4*4];
        #pragma unroll
        for (int i = 0; i < 4; i++)
            #pragma unroll
            for (int j = 0; j < 4; j++)
                acc[i][j] += av[i].x*bv[j].x + av[i].y*bv[j].y + av[i].z*bv[j].z + av[i].w*bv[j].w;
    }
    #pragma unroll
    for (int i = 0; i < 4; i++){
        size_t m = m0 + rg + 16*i;
        #pragma unroll
        for (int j = 0; j < 4; j++){
            int n = n0 + cg + 16*j;
            float val = acc[i][j] + g_bp[n];
            if (n < 256)       g_q[m*256 + n]       = __float2half_rn(val);
            else if (n < 512)  g_k[m*256 + (n-256)] = __float2half_rn(val);
            else               g_v[m*256 + (n-512)] = __float2half_rn(val);
        }
    }
}

// ---------------- HMMA fused attention (two-pass, no NxN materialization) ---
// smem layout (bytes): Q[128][264h], K[128][264h], V[128][264h], w[128]f
#define SROWB 528
#define SQO 0
#define SKO 67584
#define SVO 135168
#define SWO 202752
#define ATTN_SMEM 203264

__global__ void __launch_bounds__(256,1) k_attn(const float* __restrict__ gw){
    extern __shared__ char sm[];
    uint32_t sb = smem_u32(sm);
    int t = threadIdx.x, lane = t & 31, wid = t >> 5;
    int t4 = lane & 3, gq = lane >> 2;
    int b = blockIdx.x >> 4, qt = blockIdx.x & 15;
    size_t qrow0 = (size_t)b*NN + (size_t)qt*128;
    const char* qg  = (const char*)(g_q + qrow0*256);
    const char* kgb = (const char*)(g_k + (size_t)b*NN*256);
    const char* vgb = (const char*)(g_v + (size_t)b*NN*256);
    const float* wb = gw + (size_t)b*NN;
    float* sw = (float*)(sm + SWO);

    // load Q tile once (128 rows x 512B)
    for (int i = t; i < 4096; i += 256){
        int r = i >> 5, ch = i & 31;
        *(uint4*)(sm + SQO + r*SROWB + ch*16) = *(const uint4*)(qg + r*512 + ch*16);
    }

    int ln = lane & 15;
    uint32_t aQbase = sb + SQO + (uint32_t)(wid*16 + (lane & 15))*SROWB + (uint32_t)(lane >> 4)*16;
    uint32_t bKbase = sb + SKO + (uint32_t)(ln & 7)*SROWB + (uint32_t)((ln >> 3) & 1)*16;
    uint32_t bVbase = sb + SVO + (uint32_t)ln*SROWB;

    float llo[4] = {0,0,0,0}, lhi[4] = {0,0,0,0};

    // -------- pass 1: per-(row,head) sum-exp over all keys --------
    for (int j0 = 0; j0 < NN; j0 += 128){
        __syncthreads();
        for (int i = t; i < 4096; i += 256){
            int r = i >> 5, ch = i & 31;
            *(uint4*)(sm + SKO + r*SROWB + ch*16) = *(const uint4*)(kgb + (size_t)(j0+r)*512 + ch*16);
        }
        if (t < 128) sw[t] = wb[j0 + t];
        __syncthreads();
        #pragma unroll
        for (int h = 0; h < 4; h++){
            float sacc[16][4];
            #pragma unroll
            for (int nt = 0; nt < 16; nt++){
                sacc[nt][0] = 0.f; sacc[nt][1] = 0.f; sacc[nt][2] = 0.f; sacc[nt][3] = 0.f;
            }
            #pragma unroll
            for (int ks = 0; ks < 4; ks++){
                uint32_t aq[4];
                ldm_x4(aq, aQbase + (uint32_t)(h*64 + ks*16)*2);
                #pragma unroll
                for (int nt = 0; nt < 16; nt++){
                    uint32_t bk[2];
                    ldm_x2(bk, bKbase + (uint32_t)(nt*8)*SROWB + (uint32_t)(h*64 + ks*16)*2);
                    mma16816(sacc[nt], aq, bk);
                }
            }
            #pragma unroll
            for (int nt = 0; nt < 16; nt++){
                int jl = nt*8 + 2*t4;
                float w0 = sw[jl], w1 = sw[jl+1];
                llo[h] += (w0 != 0.f ? __expf(sacc[nt][0]*0.125f) : 0.f)
                        + (w1 != 0.f ? __expf(sacc[nt][1]*0.125f) : 0.f);
                lhi[h] += (w0 != 0.f ? __expf(sacc[nt][2]*0.125f) : 0.f)
                        + (w1 != 0.f ? __expf(sacc[nt][3]*0.125f) : 0.f);
            }
        }
    }
    #pragma unroll
    for (int h = 0; h < 4; h++){
        llo[h] += __shfl_xor_sync(0xffffffffu, llo[h], 1);
        llo[h] += __shfl_xor_sync(0xffffffffu, llo[h], 2);
        lhi[h] += __shfl_xor_sync(0xffffffffu, lhi[h], 1);
        lhi[h] += __shfl_xor_sync(0xffffffffu, lhi[h], 2);
        llo[h] = 1.f / llo[h];
        lhi[h] = 1.f / lhi[h];
    }

    // -------- pass 2: recompute scores per 32-key chunk, fused AV --------
    float out[32][4];
    #pragma unroll
    for (int dt = 0; dt < 32; dt++){
        out[dt][0] = 0.f; out[dt][1] = 0.f; out[dt][2] = 0.f; out[dt][3] = 0.f;
    }
    float zlo = 0.f, zhi = 0.f;

    for (int j0 = 0; j0 < NN; j0 += 128){
        __syncthreads();
        for (int i = t; i < 4096; i += 256){
            int r = i >> 5, ch = i & 31;
            *(uint4*)(sm + SKO + r*SROWB + ch*16) = *(const uint4*)(kgb + (size_t)(j0+r)*512 + ch*16);
            *(uint4*)(sm + SVO + r*SROWB + ch*16) = *(const uint4*)(vgb + (size_t)(j0+r)*512 + ch*16);
        }
        if (t < 128) sw[t] = wb[j0 + t];
        __syncthreads();
        #pragma unroll
        for (int cc = 0; cc < 4; cc++){
            float pacc[4][4];
            #pragma unroll
            for (int nt = 0; nt < 4; nt++){
                pacc[nt][0] = 0.f; pacc[nt][1] = 0.f; pacc[nt][2] = 0.f; pacc[nt][3] = 0.f;
            }
            #pragma unroll
            for (int h = 0; h < 4; h++){
                float sacc[4][4];
                #pragma unroll
                for (int nt = 0; nt < 4; nt++){
                    sacc[nt][0] = 0.f; sacc[nt][1] = 0.f; sacc[nt][2] = 0.f; sacc[nt][3] = 0.f;
                }
                #pragma unroll
                for (int ks = 0; ks < 4; ks++){
                    uint32_t aq[4];
                    ldm_x4(aq, aQbase + (uint32_t)(h*64 + ks*16)*2);
                    #pragma unroll
                    for (int nt = 0; nt < 4; nt++){
                        uint32_t bk[2];
                        ldm_x2(bk, bKbase + (uint32_t)(cc*32 + nt*8)*SROWB + (uint32_t)(h*64 + ks*16)*2);
                        mma16816(sacc[nt], aq, bk);
                    }
                }
                #pragma unroll
                for (int nt = 0; nt < 4; nt++){
                    pacc[nt][0] += llo[h]*__expf(sacc[nt][0]*0.125f);
                    pacc[nt][1] += llo[h]*__expf(sacc[nt][1]*0.125f);
                    pacc[nt][2] += lhi[h]*__expf(sacc[nt][2]*0.125f);
                    pacc[nt][3] += lhi[h]*__expf(sacc[nt][3]*0.125f);
                }
            }
            // multiply by w, accumulate z, convert to fp16 A-fragments
            uint32_t aP[2][4];
            #pragma unroll
            for (int nt = 0; nt < 4; nt++){
                int jl = cc*32 + nt*8 + 2*t4;
                float w0 = sw[jl], w1 = sw[jl+1];
                float c0 = pacc[nt][0]*w0, c1 = pacc[nt][1]*w1;
                float c2 = pacc[nt][2]*w0, c3 = pacc[nt][3]*w1;
                zlo += c0 + c1; zhi += c2 + c3;
                __half2 hlo = __floats2half2_rn(c0, c1);
                __half2 hhi = __floats2half2_rn(c2, c3);
                aP[nt>>1][(nt&1)*2 + 0] = *(uint32_t*)&hlo;
                aP[nt>>1][(nt&1)*2 + 1] = *(uint32_t*)&hhi;
            }
            // AV: out[16x256] += P[16x32] @ V[32x256]
            #pragma unroll
            for (int ks2 = 0; ks2 < 2; ks2++){
                uint32_t vb0 = bVbase + (uint32_t)(cc*32 + ks2*16)*SROWB;
                #pragma unroll
                for (int dt = 0; dt < 32; dt++){
                    uint32_t bv[2];
                    ldm_x2t(bv, vb0 + (uint32_t)dt*16);
                    mma16816(out[dt], aP[ks2], bv);
                }
            }
        }
    }

    // epilogue: normalize and store
    zlo += __shfl_xor_sync(0xffffffffu, zlo, 1);
    zlo += __shfl_xor_sync(0xffffffffu, zlo, 2);
    zhi += __shfl_xor_sync(0xffffffffu, zhi, 1);
    zhi += __shfl_xor_sync(0xffffffffu, zhi, 2);
    float izlo = 1.f / zlo, izhi = 1.f / zhi;
    size_t rl = qrow0 + (size_t)(wid*16 + gq);
    size_t rh = rl + 8;
    #pragma unroll
    for (int dt = 0; dt < 32; dt++){
        int col = dt*8 + 2*t4;
        *(float2*)&g_av[rl*256 + col] = make_float2(out[dt][0]*izlo, out[dt][1]*izlo);
        *(float2*)&g_av[rh*256 + col] = make_float2(out[dt][2]*izhi, out[dt][3]*izhi);
    }
}

// ---------------- out1 = x + att_out @ out_w^T + out_b ----------------------
__global__ __launch_bounds__(256) void k_out1(const float* __restrict__ ow,
                                              const float* __restrict__ ob,
                                              const float* __restrict__ x){
    __shared__ float sA[64*68];
    __shared__ float sB[64*68];
    int m0 = blockIdx.x*64;
    int t = threadIdx.x;
    int cg = t & 15, rg = t >> 4;
    float acc[4][4] = {};
    for (int kc = 0; kc < 256; kc += 64){
        __syncthreads();
        for (int i = t; i < 1024; i += 256){
            int r = i >> 4, c = i & 15;
            *(float4*)&sA[r*68 + c*4] = *(const float4*)&g_av[((size_t)(m0+r))*256 + kc + c*4];
            *(float4*)&sB[r*68 + c*4] = *(const float4*)&ow[r*256 + kc + c*4];
        }
        __syncthreads();
        #pragma unroll 4
        for (int e4 = 0; e4 < 16; e4++){
            float4 av[4], bv[4];
            #pragma unroll
            for (int i = 0; i < 4; i++) av[i] = *(const float4*)&sA[(rg+16*i)*68 + e4*4];
            #pragma unroll
            for (int j = 0; j < 4; j++) bv[j] = *(const float4*)&sB[(cg+16*j)*68 + e4*4];
            #pragma unroll
            for (int i = 0; i < 4; i++)
                #pragma unroll
                for (int j = 0; j < 4; j++)
                    acc[i][j] += av[i].x*bv[j].x + av[i].y*bv[j].y + av[i].z*bv[j].z + av[i].w*bv[j].w;
        }
    }
    #pragma unroll
    for (int i = 0; i < 4; i++){
        size_t m = m0 + rg + 16*i;
        #pragma unroll
        for (int j = 0; j < 4; j++){
            int n = cg + 16*j;
            g_o1[m*64 + n] = acc[i][j] + ob[n] + x[m*64 + n];
        }
    }
}

// ---------------- final: out = LN(out1 + softplus(LN(out1)@ffn^T + fb)) -----
__global__ __launch_bounds__(256) void k_final(const float* __restrict__ g,
                                               const float* __restrict__ be,
                                               const float* __restrict__ fw,
                                               const float* __restrict__ fb,
                                               float* __restrict__ out){
    __shared__ float sFW[64*65];
    __shared__ float sy[8][64];
    int t = threadIdx.x, lane = t & 31, w = t >> 5;
    for (int i = t; i < 4096; i += 256) sFW[(i>>6)*65 + (i&63)] = fw[i];
    __syncthreads();
    size_t row = (size_t)blockIdx.x*8 + w;
    const float* o = g_o1 + row*64;
    float o0 = o[lane], o1 = o[lane+32];
    float mean = wsum(o0+o1)*(1.f/64.f);
    float msq  = wsum(o0*o0+o1*o1)*(1.f/64.f);
    float rs = rsqrtf(msq - mean*mean + 1e-5f);
    sy[w][lane]    = (o0-mean)*rs*g[lane]    + be[lane];
    sy[w][lane+32] = (o1-mean)*rs*g[lane+32] + be[lane+32];
    __syncwarp();
    float a0 = fb[lane], a1 = fb[lane+32];
    #pragma unroll 8
    for (int c = 0; c < 64; c++){
        float yv = sy[w][c];
        a0 += yv * sFW[lane*65 + c];
        a1 += yv * sFW[(lane+32)*65 + c];
    }
    float s0 = o0 + softplusf(a0);
    float s1 = o1 + softplusf(a1);
    float m2 = wsum(s0+s1)*(1.f/64.f);
    float q2 = wsum(s0*s0+s1*s1)*(1.f/64.f);
    float r2 = rsqrtf(q2 - m2*m2 + 1e-5f);
    out[row*64 + lane]    = (s0-m2)*r2*g[lane]    + be[lane];
    out[row*64 + lane+32] = (s1-m2)*r2*g[lane+32] + be[lane+32];
}

// ---------------- launch ----------------
extern "C" void kernel_launch(void* const* d_in, const int* in_sizes, int n_in,
                              void* d_out, int out_size){
    (void)in_sizes; (void)n_in; (void)out_size;
    const float* x     = (const float*)d_in[0];
    const float* wts   = (const float*)d_in[1];
    const float* ln_g  = (const float*)d_in[2];
    const float* ln_b  = (const float*)d_in[3];
    const float* wq_w  = (const float*)d_in[4];
    const float* wq_b  = (const float*)d_in[5];
    const float* wk_w  = (const float*)d_in[6];
    const float* wk_b  = (const float*)d_in[7];
    const float* wv_w  = (const float*)d_in[8];
    const float* wv_b  = (const float*)d_in[9];
    const float* mq_w  = (const float*)d_in[10];
    const float* mq_b  = (const float*)d_in[11];
    const float* mk_w  = (const float*)d_in[12];
    const float* mk_b  = (const float*)d_in[13];
    const float* out_w = (const float*)d_in[14];
    const float* out_b = (const float*)d_in[15];
    const float* ffn_w = (const float*)d_in[16];
    const float* ffn_b = (const float*)d_in[17];
    float* out = (float*)d_out;

    cudaFuncSetAttribute(k_attn, cudaFuncAttributeMaxDynamicSharedMemorySize, ATTN_SMEM);

    k_fold<<<768, 64>>>(wq_w, wq_b, wk_w, wk_b, wv_w, wv_b, mq_w, mq_b, mk_w, mk_b);
    k_ln<<<ROWS/8, 256>>>(x, ln_g, ln_b);
    k_qkv<<<dim3(ROWS/64, 12), 256>>>();
    k_attn<<<128, 256, ATTN_SMEM>>>(wts);
    k_out1<<<ROWS/64, 256>>>(out_w, out_b, x);
    k_final<<<ROWS/8, 256>>>(ln_g, ln_b, ffn_w, ffn_b, out);
}

// round 4
// speedup vs baseline: 5.5283x; 1.0501x over previous
#include <cuda_runtime.h>
#include <cuda_fp16.h>
#include <math.h>
#include <stdint.h>

#define BB 8
#define NN 2048
#define EE 64
#define DD 256
#define ROWS (BB*NN)   // 16384

// ---------------- scratch (static device globals; no allocs) ----------------
__device__ float g_xn[ROWS*EE];
__device__ __align__(16) __half g_q[ROWS*DD];
__device__ __align__(16) __half g_k[ROWS*DD];
__device__ __align__(16) __half g_v[ROWS*DD];
__device__ __align__(16) __half g_p[(size_t)ROWS*NN];   // 64MB attention-prob scratch
__device__ float g_z[ROWS];
__device__ float g_av[ROWS*DD];
__device__ float g_o1[ROWS*EE];
__device__ float g_Wp[768*64];
__device__ float g_bp[768];

// ---------------- generic helpers ----------------
__device__ __forceinline__ float wsum(float v){
    v += __shfl_xor_sync(0xffffffffu, v, 16);
    v += __shfl_xor_sync(0xffffffffu, v, 8);
    v += __shfl_xor_sync(0xffffffffu, v, 4);
    v += __shfl_xor_sync(0xffffffffu, v, 2);
    v += __shfl_xor_sync(0xffffffffu, v, 1);
    return v;
}
__device__ __forceinline__ float softplusf(float x){
    if (x > 20.f) return x;
    return log1pf(expf(x));
}
__device__ __forceinline__ uint32_t smem_u32(const void* p){
    uint32_t a;
    asm("{ .reg .u64 t; cvta.to.shared.u64 t, %1; cvt.u32.u64 %0, t; }" : "=r"(a) : "l"(p));
    return a;
}

// ---------------- mma.sync / ldmatrix helpers (baseline PTX, sm_80+) --------
__device__ __forceinline__ void ldm_x4(uint32_t a[4], uint32_t addr){
    asm volatile("ldmatrix.sync.aligned.m8n8.x4.shared.b16 {%0,%1,%2,%3}, [%4];"
        : "=r"(a[0]), "=r"(a[1]), "=r"(a[2]), "=r"(a[3]) : "r"(addr));
}
__device__ __forceinline__ void ldm_x4t(uint32_t a[4], uint32_t addr){
    asm volatile("ldmatrix.sync.aligned.m8n8.x4.trans.shared.b16 {%0,%1,%2,%3}, [%4];"
        : "=r"(a[0]), "=r"(a[1]), "=r"(a[2]), "=r"(a[3]) : "r"(addr));
}
__device__ __forceinline__ void mma16816(float c[4], const uint32_t a[4], const uint32_t b[2]){
    asm volatile("mma.sync.aligned.m16n8k16.row.col.f32.f16.f16.f32 "
        "{%0,%1,%2,%3}, {%4,%5,%6,%7}, {%8,%9}, {%0,%1,%2,%3};"
        : "+f"(c[0]), "+f"(c[1]), "+f"(c[2]), "+f"(c[3])
        : "r"(a[0]), "r"(a[1]), "r"(a[2]), "r"(a[3]), "r"(b[0]), "r"(b[1]));
}

// ---------------- fold: W_eff = m_w @ w_w, b_eff = m_w @ w_b + m_b ----------
__global__ void k_fold(const float* __restrict__ wq_w, const float* __restrict__ wq_b,
                       const float* __restrict__ wk_w, const float* __restrict__ wk_b,
                       const float* __restrict__ wv_w, const float* __restrict__ wv_b,
                       const float* __restrict__ mq_w, const float* __restrict__ mq_b,
                       const float* __restrict__ mk_w, const float* __restrict__ mk_b){
    int r = blockIdx.x, e = threadIdx.x;
    if (r < 256){
        float acc = 0.f;
        for (int c = 0; c < 256; c++) acc += mq_w[r*256+c]*wq_w[c*64+e];
        g_Wp[r*64+e] = acc;
        if (e == 0){
            float bb = mq_b[r];
            for (int c = 0; c < 256; c++) bb += mq_w[r*256+c]*wq_b[c];
            g_bp[r] = bb;
        }
    } else if (r < 512){
        int rr = r - 256;
        float acc = 0.f;
        for (int c = 0; c < 256; c++) acc += mk_w[rr*256+c]*wk_w[c*64+e];
        g_Wp[r*64+e] = acc;
        if (e == 0){
            float bb = mk_b[rr];
            for (int c = 0; c < 256; c++) bb += mk_w[rr*256+c]*wk_b[c];
            g_bp[r] = bb;
        }
    } else {
        int rr = r - 512;
        g_Wp[r*64+e] = wv_w[rr*64+e];
        if (e == 0) g_bp[r] = wv_b[rr];
    }
}

// ---------------- LayerNorm over E=64: one warp per row ----------------
__global__ __launch_bounds__(256) void k_ln(const float* __restrict__ x,
                                            const float* __restrict__ g,
                                            const float* __restrict__ be){
    int t = threadIdx.x, lane = t & 31, w = t >> 5;
    size_t row = (size_t)blockIdx.x*8 + w;
    const float* xr = x + row*64;
    float x0 = xr[lane], x1 = xr[lane+32];
    float mean = wsum(x0+x1)*(1.f/64.f);
    float msq  = wsum(x0*x0+x1*x1)*(1.f/64.f);
    float rs = rsqrtf(msq - mean*mean + 1e-5f);
    float* o = g_xn + row*64;
    o[lane]    = (x0-mean)*rs*g[lane]    + be[lane];
    o[lane+32] = (x1-mean)*rs*g[lane+32] + be[lane+32];
}

// ---------------- QKV GEMM -> fp16 Q/K/V [row][256] --------------------------
__global__ __launch_bounds__(256) void k_qkv(){
    __shared__ float sA[64*68];
    __shared__ float sB[64*68];
    int m0 = blockIdx.x*64, n0 = blockIdx.y*64;
    int t = threadIdx.x;
    for (int i = t; i < 1024; i += 256){
        int r = i >> 4, c = i & 15;
        *(float4*)&sA[r*68 + c*4] = *(const float4*)&g_xn[((size_t)(m0+r))*64 + c*4];
        *(float4*)&sB[r*68 + c*4] = *(const float4*)&g_Wp[(n0+r)*64 + c*4];
    }
    __syncthreads();
    int cg = t & 15, rg = t >> 4;
    float acc[4][4] = {};
    #pragma unroll 4
    for (int e4 = 0; e4 < 16; e4++){
        float4 av[4], bv[4];
        #pragma unroll
        for (int i = 0; i < 4; i++) av[i] = *(const float4*)&sA[(rg+16*i)*68 + e4*4];
        #pragma unroll
        for (int j = 0; j < 4; j++) bv[j] = *(const float4*)&sB[(cg+16*j)*68 + e4*4];
        #pragma unroll
        for (int i = 0; i < 4; i++)
            #pragma unroll
            for (int j = 0; j < 4; j++)
                acc[i][j] += av[i].x*bv[j].x + av[i].y*bv[j].y + av[i].z*bv[j].z + av[i].w*bv[j].w;
    }
    #pragma unroll
    for (int i = 0; i < 4; i++){
        size_t m = m0 + rg + 16*i;
        #pragma unroll
        for (int j = 0; j < 4; j++){
            int n = n0 + cg + 16*j;
            float val = acc[i][j] + g_bp[n];
            if (n < 256)       g_q[m*256 + n]       = __float2half_rn(val);
            else if (n < 512)  g_k[m*256 + (n-256)] = __float2half_rn(val);
            else               g_v[m*256 + (n-512)] = __float2half_rn(val);
        }
    }
}

// ---------------- k_score: two-pass scores -> P (fp16, global) + 1/z --------
// 512 threads = 16 warps: wq = wid&3 (32-row group), wk = wid>>2 (32-key group)
#define SC_SQO 0
#define SC_SKO 67584
#define SC_SWO 135168
#define SC_SLO 135680
#define SC_SMEM 143872

__global__ void __launch_bounds__(512,1) k_score(const float* __restrict__ gw){
    extern __shared__ char sm[];
    uint32_t sb = smem_u32(sm);
    int t = threadIdx.x, lane = t & 31, wid = t >> 5;
    int t4 = lane & 3, gq = lane >> 2;
    int wq = wid & 3, wk = wid >> 2;
    int b = blockIdx.x >> 4, qt = blockIdx.x & 15;
    size_t qrow0 = (size_t)b*NN + (size_t)qt*128;
    const char*  qg  = (const char*)(g_q + qrow0*256);
    const char*  kgb = (const char*)(g_k + (size_t)b*NN*256);
    const float* wb  = gw + (size_t)b*NN;
    float* sw = (float*)(sm + SC_SWO);
    float* sL = (float*)(sm + SC_SLO);

    // Q tile resident (128 x 512B, pitch 528)
    for (int i = t; i < 4096; i += 512){
        int r = i >> 5, c = i & 31;
        *(uint4*)(sm + SC_SQO + r*528 + c*16) = *(const uint4*)(qg + r*512 + c*16);
    }

    uint32_t lo16 = lane & 15, hi16 = lane >> 4;
    uint32_t aQb = sb + SC_SQO + (uint32_t)(wq*32 + lo16)*528 + hi16*16;
    uint32_t kl  = (uint32_t)((lane & 7) + ((lane >> 4) << 3));
    uint32_t bKb = sb + SC_SKO + (uint32_t)(wk*32)*528 + kl*528 + (uint32_t)((lane >> 3) & 1)*16;

    // -------- pass 1: l_h per (row, head) --------
    float lacc[2][2][4];
    #pragma unroll
    for (int mb = 0; mb < 2; mb++)
        #pragma unroll
        for (int hf = 0; hf < 2; hf++)
            #pragma unroll
            for (int h = 0; h < 4; h++) lacc[mb][hf][h] = 0.f;

    for (int j0 = 0; j0 < NN; j0 += 128){
        __syncthreads();
        for (int i = t; i < 4096; i += 512){
            int r = i >> 5, c = i & 31;
            *(uint4*)(sm + SC_SKO + r*528 + c*16) = *(const uint4*)(kgb + (size_t)(j0+r)*512 + c*16);
        }
        if (t < 128) sw[t] = wb[j0 + t];
        __syncthreads();
        #pragma unroll
        for (int h = 0; h < 4; h++){
            float sacc[2][4][4];
            #pragma unroll
            for (int mb = 0; mb < 2; mb++)
                #pragma unroll
                for (int nt = 0; nt < 4; nt++)
                    #pragma unroll
                    for (int q = 0; q < 4; q++) sacc[mb][nt][q] = 0.f;
            #pragma unroll
            for (int ks = 0; ks < 4; ks++){
                uint32_t hk = (uint32_t)(h*64 + ks*16)*2;
                uint32_t aq[2][4];
                ldm_x4(aq[0], aQb + hk);
                ldm_x4(aq[1], aQb + 16u*528 + hk);
                #pragma unroll
                for (int ntp = 0; ntp < 2; ntp++){
                    uint32_t kf[4];
                    ldm_x4(kf, bKb + (uint32_t)(ntp*16)*528 + hk);
                    #pragma unroll
                    for (int mb = 0; mb < 2; mb++){
                        mma16816(sacc[mb][ntp*2],   aq[mb], kf);
                        mma16816(sacc[mb][ntp*2+1], aq[mb], kf+2);
                    }
                }
            }
            #pragma unroll
            for (int mb = 0; mb < 2; mb++)
                #pragma unroll
                for (int nt = 0; nt < 4; nt++){
                    int key = wk*32 + nt*8 + 2*t4;
                    float w0 = sw[key], w1 = sw[key+1];
                    lacc[mb][0][h] += (w0 != 0.f ? __expf(sacc[mb][nt][0]*0.125f) : 0.f)
                                    + (w1 != 0.f ? __expf(sacc[mb][nt][1]*0.125f) : 0.f);
                    lacc[mb][1][h] += (w0 != 0.f ? __expf(sacc[mb][nt][2]*0.125f) : 0.f)
                                    + (w1 != 0.f ? __expf(sacc[mb][nt][3]*0.125f) : 0.f);
                }
        }
    }
    // reduce l across key-quad and key-group warps
    #pragma unroll
    for (int mb = 0; mb < 2; mb++)
        #pragma unroll
        for (int hf = 0; hf < 2; hf++)
            #pragma unroll
            for (int h = 0; h < 4; h++){
                float v = lacc[mb][hf][h];
                v += __shfl_xor_sync(0xffffffffu, v, 1);
                v += __shfl_xor_sync(0xffffffffu, v, 2);
                if (t4 == 0){
                    int row = wq*32 + mb*16 + hf*8 + gq;
                    sL[(wk*128 + row)*4 + h] = v;
                }
            }
    __syncthreads();
    float ilv[2][2][4];
    #pragma unroll
    for (int mb = 0; mb < 2; mb++)
        #pragma unroll
        for (int hf = 0; hf < 2; hf++){
            int row = wq*32 + mb*16 + hf*8 + gq;
            #pragma unroll
            for (int h = 0; h < 4; h++){
                float s = sL[row*4+h] + sL[(128+row)*4+h] + sL[(256+row)*4+h] + sL[(384+row)*4+h];
                ilv[mb][hf][h] = 1.f / s;
            }
        }
    __syncthreads();

    // -------- pass 2: c = w * sum_h exp(s)/l_h -> P fp16 (global), z --------
    float zp[2][2] = {{0.f,0.f},{0.f,0.f}};
    for (int j0 = 0; j0 < NN; j0 += 128){
        __syncthreads();
        for (int i = t; i < 4096; i += 512){
            int r = i >> 5, c = i & 31;
            *(uint4*)(sm + SC_SKO + r*528 + c*16) = *(const uint4*)(kgb + (size_t)(j0+r)*512 + c*16);
        }
        if (t < 128) sw[t] = wb[j0 + t];
        __syncthreads();
        float pacc[2][4][4];
        #pragma unroll
        for (int mb = 0; mb < 2; mb++)
            #pragma unroll
            for (int nt = 0; nt < 4; nt++)
                #pragma unroll
                for (int q = 0; q < 4; q++) pacc[mb][nt][q] = 0.f;
        #pragma unroll
        for (int h = 0; h < 4; h++){
            float sacc[2][4][4];
            #pragma unroll
            for (int mb = 0; mb < 2; mb++)
                #pragma unroll
                for (int nt = 0; nt < 4; nt++)
                    #pragma unroll
                    for (int q = 0; q < 4; q++) sacc[mb][nt][q] = 0.f;
            #pragma unroll
            for (int ks = 0; ks < 4; ks++){
                uint32_t hk = (uint32_t)(h*64 + ks*16)*2;
                uint32_t aq[2][4];
                ldm_x4(aq[0], aQb + hk);
                ldm_x4(aq[1], aQb + 16u*528 + hk);
                #pragma unroll
                for (int ntp = 0; ntp < 2; ntp++){
                    uint32_t kf[4];
                    ldm_x4(kf, bKb + (uint32_t)(ntp*16)*528 + hk);
                    #pragma unroll
                    for (int mb = 0; mb < 2; mb++){
                        mma16816(sacc[mb][ntp*2],   aq[mb], kf);
                        mma16816(sacc[mb][ntp*2+1], aq[mb], kf+2);
                    }
                }
            }
            #pragma unroll
            for (int mb = 0; mb < 2; mb++)
                #pragma unroll
                for (int nt = 0; nt < 4; nt++){
                    pacc[mb][nt][0] += ilv[mb][0][h]*__expf(sacc[mb][nt][0]*0.125f);
                    pacc[mb][nt][1] += ilv[mb][0][h]*__expf(sacc[mb][nt][1]*0.125f);
                    pacc[mb][nt][2] += ilv[mb][1][h]*__expf(sacc[mb][nt][2]*0.125f);
                    pacc[mb][nt][3] += ilv[mb][1][h]*__expf(sacc[mb][nt][3]*0.125f);
                }
        }
        #pragma unroll
        for (int mb = 0; mb < 2; mb++){
            size_t rA = qrow0 + (size_t)(wq*32 + mb*16 + gq);
            size_t rB = rA + 8;
            #pragma unroll
            for (int nt = 0; nt < 4; nt++){
                int kloc = wk*32 + nt*8 + 2*t4;
                float w0 = sw[kloc], w1 = sw[kloc+1];
                float c0 = pacc[mb][nt][0]*w0, c1 = pacc[mb][nt][1]*w1;
                float c2 = pacc[mb][nt][2]*w0, c3 = pacc[mb][nt][3]*w1;
                zp[mb][0] += c0 + c1;
                zp[mb][1] += c2 + c3;
                size_t key = (size_t)(j0 + kloc);
                *(__half2*)&g_p[rA*NN + key] = __floats2half2_rn(c0, c1);
                *(__half2*)&g_p[rB*NN + key] = __floats2half2_rn(c2, c3);
            }
        }
    }
    // z reduction -> g_z = 1/z
    float* sZ = sL;
    #pragma unroll
    for (int mb = 0; mb < 2; mb++)
        #pragma unroll
        for (int hf = 0; hf < 2; hf++){
            float v = zp[mb][hf];
            v += __shfl_xor_sync(0xffffffffu, v, 1);
            v += __shfl_xor_sync(0xffffffffu, v, 2);
            if (t4 == 0){
                int row = wq*32 + mb*16 + hf*8 + gq;
                sZ[wk*128 + row] = v;
            }
        }
    __syncthreads();
    if (wk == 0 && t4 == 0){
        #pragma unroll
        for (int mb = 0; mb < 2; mb++)
            #pragma unroll
            for (int hf = 0; hf < 2; hf++){
                int row = wq*32 + mb*16 + hf*8 + gq;
                float z = sZ[row] + sZ[128+row] + sZ[256+row] + sZ[384+row];
                g_z[qrow0 + row] = 1.f / z;
            }
    }
}

// ---------------- k_av: out = (P @ V) / z -----------------------------------
// 512 threads = 16 warps: wq = wid&3 (32-row group), wd = wid>>2 (64-D quarter)
#define AV_SPO 0
#define AV_SVO 34816
#define AV_SMEM 102400

__global__ void __launch_bounds__(512,1) k_av(){
    extern __shared__ char sm[];
    uint32_t sb = smem_u32(sm);
    int t = threadIdx.x, lane = t & 31, wid = t >> 5;
    int t4 = lane & 3, gq = lane >> 2;
    int wq = wid & 3, wd = wid >> 2;
    size_t row0 = (size_t)blockIdx.x*128;
    int b = blockIdx.x >> 4;
    const char* pg  = (const char*)g_p + row0*NN*2;
    const char* vgb = (const char*)(g_v + (size_t)b*NN*256);

    uint32_t lo16 = lane & 15, hi16 = lane >> 4;
    uint32_t aPb = sb + AV_SPO + (uint32_t)(wq*32 + lo16)*272 + hi16*16;
    uint32_t bVb = sb + AV_SVO + lo16*528 + (uint32_t)wd*128 + hi16*16;

    float out[2][8][4];
    #pragma unroll
    for (int mb = 0; mb < 2; mb++)
        #pragma unroll
        for (int nt = 0; nt < 8; nt++)
            #pragma unroll
            for (int q = 0; q < 4; q++) out[mb][nt][q] = 0.f;

    for (int j0 = 0; j0 < NN; j0 += 128){
        __syncthreads();
        for (int i = t; i < 2048; i += 512){
            int r = i >> 4, c = i & 15;
            *(uint4*)(sm + AV_SPO + r*272 + c*16) = *(const uint4*)(pg + (size_t)r*(NN*2) + (size_t)j0*2 + c*16);
        }
        for (int i = t; i < 4096; i += 512){
            int r = i >> 5, c = i & 31;
            *(uint4*)(sm + AV_SVO + r*528 + c*16) = *(const uint4*)(vgb + (size_t)(j0+r)*512 + c*16);
        }
        __syncthreads();
        #pragma unroll
        for (int ks = 0; ks < 8; ks++){
            uint32_t ap[2][4];
            ldm_x4(ap[0], aPb + (uint32_t)ks*32);
            ldm_x4(ap[1], aPb + 16u*272 + (uint32_t)ks*32);
            #pragma unroll
            for (int dt2 = 0; dt2 < 4; dt2++){
                uint32_t vf[4];
                ldm_x4t(vf, bVb + (uint32_t)(ks*16)*528 + (uint32_t)dt2*32);
                mma16816(out[0][dt2*2],   ap[0], vf);
                mma16816(out[0][dt2*2+1], ap[0], vf+2);
                mma16816(out[1][dt2*2],   ap[1], vf);
                mma16816(out[1][dt2*2+1], ap[1], vf+2);
            }
        }
    }
    #pragma unroll
    for (int mb = 0; mb < 2; mb++){
        size_t rA = row0 + (size_t)(wq*32 + mb*16 + gq);
        size_t rB = rA + 8;
        float izA = g_z[rA], izB = g_z[rB];
        #pragma unroll
        for (int nt = 0; nt < 8; nt++){
            int col = wd*64 + nt*8 + 2*t4;
            *(float2*)&g_av[rA*256 + col] = make_float2(out[mb][nt][0]*izA, out[mb][nt][1]*izA);
            *(float2*)&g_av[rB*256 + col] = make_float2(out[mb][nt][2]*izB, out[mb][nt][3]*izB);
        }
    }
}

// ---------------- out1 = x + att_out @ out_w^T + out_b ----------------------
__global__ __launch_bounds__(256) void k_out1(const float* __restrict__ ow,
                                              const float* __restrict__ ob,
                                              const float* __restrict__ x){
    __shared__ float sA[64*68];
    __shared__ float sB[64*68];
    int m0 = blockIdx.x*64;
    int t = threadIdx.x;
    int cg = t & 15, rg = t >> 4;
    float acc[4][4] = {};
    for (int kc = 0; kc < 256; kc += 64){
        __syncthreads();
        for (int i = t; i < 1024; i += 256){
            int r = i >> 4, c = i & 15;
            *(float4*)&sA[r*68 + c*4] = *(const float4*)&g_av[((size_t)(m0+r))*256 + kc + c*4];
            *(float4*)&sB[r*68 + c*4] = *(const float4*)&ow[r*256 + kc + c*4];
        }
        __syncthreads();
        #pragma unroll 4
        for (int e4 = 0; e4 < 16; e4++){
            float4 av[4], bv[4];
            #pragma unroll
            for (int i = 0; i < 4; i++) av[i] = *(const float4*)&sA[(rg+16*i)*68 + e4*4];
            #pragma unroll
            for (int j = 0; j < 4; j++) bv[j] = *(const float4*)&sB[(cg+16*j)*68 + e4*4];
            #pragma unroll
            for (int i = 0; i < 4; i++)
                #pragma unroll
                for (int j = 0; j < 4; j++)
                    acc[i][j] += av[i].x*bv[j].x + av[i].y*bv[j].y + av[i].z*bv[j].z + av[i].w*bv[j].w;
        }
    }
    #pragma unroll
    for (int i = 0; i < 4; i++){
        size_t m = m0 + rg + 16*i;
        #pragma unroll
        for (int j = 0; j < 4; j++){
            int n = cg + 16*j;
            g_o1[m*64 + n] = acc[i][j] + ob[n] + x[m*64 + n];
        }
    }
}

// ---------------- final: out = LN(out1 + softplus(LN(out1)@ffn^T + fb)) -----
__global__ __launch_bounds__(256) void k_final(const float* __restrict__ g,
                                               const float* __restrict__ be,
                                               const float* __restrict__ fw,
                                               const float* __restrict__ fb,
                                               float* __restrict__ out){
    __shared__ float sFW[64*65];
    __shared__ float sy[8][64];
    int t = threadIdx.x, lane = t & 31, w = t >> 5;
    for (int i = t; i < 4096; i += 256) sFW[(i>>6)*65 + (i&63)] = fw[i];
    __syncthreads();
    size_t row = (size_t)blockIdx.x*8 + w;
    const float* o = g_o1 + row*64;
    float o0 = o[lane], o1 = o[lane+32];
    float mean = wsum(o0+o1)*(1.f/64.f);
    float msq  = wsum(o0*o0+o1*o1)*(1.f/64.f);
    float rs = rsqrtf(msq - mean*mean + 1e-5f);
    sy[w][lane]    = (o0-mean)*rs*g[lane]    + be[lane];
    sy[w][lane+32] = (o1-mean)*rs*g[lane+32] + be[lane+32];
    __syncwarp();
    float a0 = fb[lane], a1 = fb[lane+32];
    #pragma unroll 8
    for (int c = 0; c < 64; c++){
        float yv = sy[w][c];
        a0 += yv * sFW[lane*65 + c];
        a1 += yv * sFW[(lane+32)*65 + c];
    }
    float s0 = o0 + softplusf(a0);
    float s1 = o1 + softplusf(a1);
    float m2 = wsum(s0+s1)*(1.f/64.f);
    float q2 = wsum(s0*s0+s1*s1)*(1.f/64.f);
    float r2 = rsqrtf(q2 - m2*m2 + 1e-5f);
    out[row*64 + lane]    = (s0-m2)*r2*g[lane]    + be[lane];
    out[row*64 + lane+32] = (s1-m2)*r2*g[lane+32] + be[lane+32];
}

// ---------------- launch ----------------
extern "C" void kernel_launch(void* const* d_in, const int* in_sizes, int n_in,
                              void* d_out, int out_size){
    (void)in_sizes; (void)n_in; (void)out_size;
    const float* x     = (const float*)d_in[0];
    const float* wts   = (const float*)d_in[1];
    const float* ln_g  = (const float*)d_in[2];
    const float* ln_b  = (const float*)d_in[3];
    const float* wq_w  = (const float*)d_in[4];
    const float* wq_b  = (const float*)d_in[5];
    const float* wk_w  = (const float*)d_in[6];
    const float* wk_b  = (const float*)d_in[7];
    const float* wv_w  = (const float*)d_in[8];
    const float* wv_b  = (const float*)d_in[9];
    const float* mq_w  = (const float*)d_in[10];
    const float* mq_b  = (const float*)d_in[11];
    const float* mk_w  = (const float*)d_in[12];
    const float* mk_b  = (const float*)d_in[13];
    const float* out_w = (const float*)d_in[14];
    const float* out_b = (const float*)d_in[15];
    const float* ffn_w = (const float*)d_in[16];
    const float* ffn_b = (const float*)d_in[17];
    float* out = (float*)d_out;

    cudaFuncSetAttribute(k_score, cudaFuncAttributeMaxDynamicSharedMemorySize, SC_SMEM);
    cudaFuncSetAttribute(k_av,    cudaFuncAttributeMaxDynamicSharedMemorySize, AV_SMEM);

    k_fold<<<768, 64>>>(wq_w, wq_b, wk_w, wk_b, wv_w, wv_b, mq_w, mq_b, mk_w, mk_b);
    k_ln<<<ROWS/8, 256>>>(x, ln_g, ln_b);
    k_qkv<<<dim3(ROWS/64, 12), 256>>>();
    k_score<<<128, 512, SC_SMEM>>>(wts);
    k_av<<<128, 512, AV_SMEM>>>();
    k_out1<<<ROWS/64, 256>>>(out_w, out_b, x);
    k_final<<<ROWS/8, 256>>>(ln_g, ln_b, ffn_w, ffn_b, out);
}